// round 2
// baseline (speedup 1.0000x reference)
#include <cuda_runtime.h>
#include <cuda_bf16.h>

#define NN 40000
#define EE 640000
#define HH 128
#define GG 16
#define CC 10

// Scratch (static device globals; no allocation at runtime). 16B aligned for float4.
__device__ __align__(16) float g_h[NN * HH];     // current activation
__device__ __align__(16) float g_g[NN * HH];     // g = (h@W) * dis
__device__ __align__(16) float g_acc[NN * HH];   // scatter accumulator
__device__ __align__(16) float g_dis[NN];        // deg -> deg_inv_sqrt (in place)
__device__ __align__(16) float g_pool[GG * HH + GG];  // pooled sums + counts

// ---------------------------------------------------------------------------
// degree: atomicAdd 1 per edge at dst
__global__ void deg_kernel(const int* __restrict__ dst) {
    int e = blockIdx.x * blockDim.x + threadIdx.x;
    if (e < EE) atomicAdd(&g_dis[dst[e]], 1.0f);
}

__global__ void dis_kernel() {
    int i = blockIdx.x * blockDim.x + threadIdx.x;
    if (i < NN) g_dis[i] = rsqrtf(g_dis[i] + 1.0f);
}

// ---------------------------------------------------------------------------
// GEMM: out[M,128] = A[M,128] @ W[128,128], epilogue:
//   EPI==0: out += bias[col]
//   EPI==1: out *= dis[row]
// BM=64, BN=128, full K=128 in smem. 256 threads, each computes 4 rows x 8 cols.
template <int EPI>
__global__ void gemm128(const float* __restrict__ A,
                        const float* __restrict__ W,
                        const float* __restrict__ bias_or_dis,
                        float* __restrict__ out) {
    extern __shared__ float smem[];
    float* Xs = smem;            // 64*128
    float* Ws = smem + 64 * 128; // 128*128

    const int tid = threadIdx.x;
    const int row0 = blockIdx.x * 64;

    // Load W (4096 float4s, 16 per thread)
    const float4* W4 = (const float4*)W;
    float4* Ws4 = (float4*)Ws;
#pragma unroll
    for (int i = 0; i < 16; i++) Ws4[tid + 256 * i] = W4[tid + 256 * i];

    // Load X tile (2048 float4s, 8 per thread)
    const float4* A4 = (const float4*)(A + (size_t)row0 * 128);
    float4* Xs4 = (float4*)Xs;
#pragma unroll
    for (int i = 0; i < 8; i++) Xs4[tid + 256 * i] = A4[tid + 256 * i];

    __syncthreads();

    const int tx = tid & 15;   // col group: cols tx*8 .. tx*8+7
    const int ty = tid >> 4;   // row group: rows ty*4 .. ty*4+3

    float acc[4][8];
#pragma unroll
    for (int i = 0; i < 4; i++)
#pragma unroll
        for (int j = 0; j < 8; j++) acc[i][j] = 0.0f;

    const float* xp = Xs + ty * 4 * 128;
    const float* wp = Ws + tx * 8;

#pragma unroll 8
    for (int k = 0; k < 128; k++) {
        float4 w0 = *(const float4*)(wp + k * 128);
        float4 w1 = *(const float4*)(wp + k * 128 + 4);
        float x0 = xp[k];
        float x1 = xp[k + 128];
        float x2 = xp[k + 256];
        float x3 = xp[k + 384];
        float wv[8] = {w0.x, w0.y, w0.z, w0.w, w1.x, w1.y, w1.z, w1.w};
        float xv[4] = {x0, x1, x2, x3};
#pragma unroll
        for (int i = 0; i < 4; i++)
#pragma unroll
            for (int j = 0; j < 8; j++) acc[i][j] += xv[i] * wv[j];
    }

    // Epilogue
#pragma unroll
    for (int i = 0; i < 4; i++) {
        int r = row0 + ty * 4 + i;
        float* op = out + (size_t)r * 128 + tx * 8;
        if (EPI == 0) {
            const float* bp = bias_or_dis + tx * 8;
#pragma unroll
            for (int j = 0; j < 8; j++) op[j] = acc[i][j] + bp[j];
        } else {
            float s = bias_or_dis[r];
#pragma unroll
            for (int j = 0; j < 8; j++) op[j] = acc[i][j] * s;
        }
    }
}

// ---------------------------------------------------------------------------
// Scatter: one warp per edge; acc[dst] += g[src] (vectorized red.global)
__global__ void scatter_kernel(const int* __restrict__ src,
                               const int* __restrict__ dst) {
    int w = (blockIdx.x * blockDim.x + threadIdx.x) >> 5;
    if (w >= EE) return;
    int lane = threadIdx.x & 31;
    int s = src[w];
    int d = dst[w];
    float4 v = *(const float4*)(g_g + (size_t)s * 128 + lane * 4);
    float* p = g_acc + (size_t)d * 128 + lane * 4;
    asm volatile("red.global.add.v4.f32 [%0], {%1,%2,%3,%4};"
                 :: "l"(p), "f"(v.x), "f"(v.y), "f"(v.z), "f"(v.w)
                 : "memory");
}

// ---------------------------------------------------------------------------
// finalize: h = relu(dis[n]*(acc+g) + b[col])   (float4 over N*32 items)
__global__ void finalize_kernel(const float* __restrict__ b) {
    int idx = blockIdx.x * blockDim.x + threadIdx.x;  // 0 .. N*32-1
    if (idx >= NN * 32) return;
    int n = idx >> 5;
    int c4 = idx & 31;
    float s = g_dis[n];
    float4 a = *(const float4*)(g_acc + (size_t)idx * 4);
    float4 g = *(const float4*)(g_g + (size_t)idx * 4);
    float4 bb = *(const float4*)(b + c4 * 4);
    float4 o;
    o.x = fmaxf(fmaf(s, a.x + g.x, bb.x), 0.0f);
    o.y = fmaxf(fmaf(s, a.y + g.y, bb.y), 0.0f);
    o.z = fmaxf(fmaf(s, a.z + g.z, bb.z), 0.0f);
    o.w = fmaxf(fmaf(s, a.w + g.w, bb.w), 0.0f);
    *(float4*)(g_h + (size_t)idx * 4) = o;
}

// ---------------------------------------------------------------------------
// Pool: per-block smem accumulator [16][128] + counts, flushed with atomics
__global__ void pool_kernel(const int* __restrict__ batch) {
    __shared__ float s[GG * HH];
    __shared__ float c[GG];
    int tid = threadIdx.x;  // 128 threads
#pragma unroll
    for (int i = 0; i < GG; i++) s[i * HH + tid] = 0.0f;
    if (tid < GG) c[tid] = 0.0f;
    __syncthreads();

    for (int n = blockIdx.x; n < NN; n += gridDim.x) {
        int b = batch[n];
        s[b * HH + tid] += g_h[(size_t)n * HH + tid];
        if (tid == 0) c[b] += 1.0f;
    }
    __syncthreads();
#pragma unroll
    for (int i = 0; i < GG; i++) atomicAdd(&g_pool[i * HH + tid], s[i * HH + tid]);
    if (tid < GG) atomicAdd(&g_pool[GG * HH + tid], c[tid]);
}

// ---------------------------------------------------------------------------
// Head: pooled mean -> relu(@Wf1+bf1) -> @Wf2+bf2. Single block, 1024 threads.
__global__ void head_kernel(const float* __restrict__ Wf1,
                            const float* __restrict__ bf1,
                            const float* __restrict__ Wf2,
                            const float* __restrict__ bf2,
                            float* __restrict__ out) {
    __shared__ float P[GG * HH];   // pooled means
    __shared__ float Z[GG * 64];
    int tid = threadIdx.x;

    // pooled means
    for (int i = tid; i < GG * HH; i += 1024) {
        float cnt = g_pool[GG * HH + i / HH];
        P[i] = g_pool[i] / fmaxf(cnt, 1.0f);
    }
    __syncthreads();

    // Z[g][j] = relu(sum_k P[g][k]*Wf1[k][j] + bf1[j])
    {
        int g = tid >> 6;      // 0..15
        int j = tid & 63;      // 0..63
        float acc = bf1[j];
        const float* p = P + g * HH;
#pragma unroll 8
        for (int k = 0; k < HH; k++) acc += p[k] * Wf1[k * 64 + j];
        Z[g * 64 + j] = fmaxf(acc, 0.0f);
    }
    __syncthreads();

    // out[g][c] = sum_j Z[g][j]*Wf2[j][c] + bf2[c]
    if (tid < GG * CC) {
        int g = tid / CC;
        int c = tid % CC;
        float acc = bf2[c];
        const float* z = Z + g * 64;
#pragma unroll
        for (int j = 0; j < 64; j++) acc += z[j] * Wf2[j * CC + c];
        out[g * CC + c] = acc;
    }
}

// ---------------------------------------------------------------------------
extern "C" void kernel_launch(void* const* d_in, const int* in_sizes, int n_in,
                              void* d_out, int out_size) {
    const float* x = (const float*)d_in[0];
    const int* edge = (const int*)d_in[1];     // int32 (JAX default, no x64)
    const int* batch = (const int*)d_in[2];    // int32
    const float* W_in = (const float*)d_in[3];
    const float* b_in = (const float*)d_in[4];
    const float* W1 = (const float*)d_in[5];
    const float* b1 = (const float*)d_in[6];
    const float* W2 = (const float*)d_in[7];
    const float* b2 = (const float*)d_in[8];
    const float* Wf1 = (const float*)d_in[9];
    const float* bf1 = (const float*)d_in[10];
    const float* Wf2 = (const float*)d_in[11];
    const float* bf2 = (const float*)d_in[12];
    float* out = (float*)d_out;

    const int* src = edge;
    const int* dst = edge + EE;

    void *p_dis, *p_acc, *p_pool, *p_h, *p_g;
    cudaGetSymbolAddress(&p_dis, g_dis);
    cudaGetSymbolAddress(&p_acc, g_acc);
    cudaGetSymbolAddress(&p_pool, g_pool);
    cudaGetSymbolAddress(&p_h, g_h);
    cudaGetSymbolAddress(&p_g, g_g);
    float* f_h = (float*)p_h;
    float* f_g = (float*)p_g;

    const int smemGemm = (64 * 128 + 128 * 128) * sizeof(float);  // 96KB
    cudaFuncSetAttribute(gemm128<0>, cudaFuncAttributeMaxDynamicSharedMemorySize, smemGemm);
    cudaFuncSetAttribute(gemm128<1>, cudaFuncAttributeMaxDynamicSharedMemorySize, smemGemm);

    // deg -> dis
    cudaMemsetAsync(p_dis, 0, NN * sizeof(float));
    deg_kernel<<<(EE + 255) / 256, 256>>>(dst);
    dis_kernel<<<(NN + 255) / 256, 256>>>();

    // h0 = x @ W_in + b_in
    gemm128<0><<<NN / 64, 256, smemGemm>>>(x, W_in, b_in, f_h);

    // Layer 1
    gemm128<1><<<NN / 64, 256, smemGemm>>>(f_h, W1, (const float*)p_dis, f_g);
    cudaMemsetAsync(p_acc, 0, (size_t)NN * HH * sizeof(float));
    scatter_kernel<<<(EE * 32 + 255) / 256, 256>>>(src, dst);
    finalize_kernel<<<(NN * 32 + 255) / 256, 256>>>(b1);

    // Layer 2
    gemm128<1><<<NN / 64, 256, smemGemm>>>(f_h, W2, (const float*)p_dis, f_g);
    cudaMemsetAsync(p_acc, 0, (size_t)NN * HH * sizeof(float));
    scatter_kernel<<<(EE * 32 + 255) / 256, 256>>>(src, dst);
    finalize_kernel<<<(NN * 32 + 255) / 256, 256>>>(b2);

    // Pool + head
    cudaMemsetAsync(p_pool, 0, (GG * HH + GG) * sizeof(float));
    pool_kernel<<<256, 128>>>(batch);
    head_kernel<<<1, 1024>>>(Wf1, bf1, Wf2, bf2, out);
}

// round 3
// speedup vs baseline: 1.4805x; 1.4805x over previous
#include <cuda_runtime.h>
#include <cuda_bf16.h>

#define NN 40000
#define NP 40064          // padded to multiple of 64
#define EE 640000
#define HH 128
#define GG 16
#define CC 10
#define XSTR 68           // Xs row stride (64 + 4 pad, multiple of 4 for LDS.128)

// Scratch (static device globals). 16B aligned for float4.
__device__ __align__(16) float g_h[NP * HH];     // activations
__device__ __align__(16) float g_g[NP * HH];     // g = (h@W) * dis
__device__ __align__(16) float g_dis[NP];        // deg_inv_sqrt
__device__ int   g_deg[NN];                      // in-degree
__device__ int   g_rowptr[NN + 1];
__device__ int   g_cursor[NN];
__device__ int   g_col[EE];
__device__ __align__(16) float g_pool[GG * HH + GG];

// ---------------------------------------------------------------------------
__global__ void deg_kernel(const int* __restrict__ dst) {
    int e = blockIdx.x * blockDim.x + threadIdx.x;
    if (e < EE) atomicAdd(&g_deg[dst[e]], 1);
}

__global__ void dis_kernel() {
    int i = blockIdx.x * blockDim.x + threadIdx.x;
    if (i < NN) g_dis[i] = rsqrtf((float)g_deg[i] + 1.0f);
}

// Exclusive scan of g_deg -> g_rowptr (+ copy to g_cursor). One block, 1024 thr.
__global__ void scan_kernel() {
    __shared__ int s[1024];
    const int CH = 40;  // 1024*40 = 40960 >= NN
    int t = threadIdx.x;
    int base = t * CH;
    int sum = 0;
    for (int i = 0; i < CH; i++) {
        int n = base + i;
        if (n < NN) sum += g_deg[n];
    }
    s[t] = sum;
    __syncthreads();
    for (int off = 1; off < 1024; off <<= 1) {
        int v = (t >= off) ? s[t - off] : 0;
        __syncthreads();
        s[t] += v;
        __syncthreads();
    }
    int run = (t == 0) ? 0 : s[t - 1];
    for (int i = 0; i < CH; i++) {
        int n = base + i;
        if (n < NN) {
            g_rowptr[n] = run;
            g_cursor[n] = run;
            run += g_deg[n];
        }
    }
    if (t == 1023) g_rowptr[NN] = EE;
}

__global__ void fill_kernel(const int* __restrict__ src,
                            const int* __restrict__ dst) {
    int e = blockIdx.x * blockDim.x + threadIdx.x;
    if (e < EE) {
        int pos = atomicAdd(&g_cursor[dst[e]], 1);
        g_col[pos] = src[e];
    }
}

// ---------------------------------------------------------------------------
// GEMM: out[NP,128] = A[?,128] @ W[128,128]. 64x128 tile, 128 threads, 8x8/thr.
// Xs stored transposed [k][m] (stride XSTR). EPI 0: +bias[col]; EPI 1: *dis[row].
template <int EPI>
__global__ void gemm128(const float* __restrict__ A,
                        const float* __restrict__ W,
                        const float* __restrict__ bias_or_dis,
                        float* __restrict__ out, int mclamp) {
    extern __shared__ float smem[];
    float* Xs = smem;                 // [128][XSTR]
    float* Ws = smem + 128 * XSTR;    // [128][128]

    const int tid = threadIdx.x;      // 128 threads
    const int row0 = blockIdx.x * 64;

    // Load W: 4096 float4s, 32 per thread, linear copy (conflict-free STS.128)
    const float4* W4 = (const float4*)W;
    float4* Ws4 = (float4*)Ws;
#pragma unroll
    for (int i = 0; i < 32; i++) Ws4[i * 128 + tid] = W4[i * 128 + tid];

    // Load X tile transposed: 2048 float4s, 16 per thread.
    // idx -> kq (float4 index in k, 0..31), row (0..63)
#pragma unroll
    for (int i = 0; i < 16; i++) {
        int idx = i * 128 + tid;
        int kq = (idx & 3) | ((idx >> 8) << 2);
        int row = (idx >> 2) & 63;
        int gr = row0 + row;
        if (gr > mclamp) gr = mclamp;
        float4 v = *(const float4*)(A + (size_t)gr * 128 + kq * 4);
        Xs[(kq * 4 + 0) * XSTR + row] = v.x;
        Xs[(kq * 4 + 1) * XSTR + row] = v.y;
        Xs[(kq * 4 + 2) * XSTR + row] = v.z;
        Xs[(kq * 4 + 3) * XSTR + row] = v.w;
    }
    __syncthreads();

    const int tx = tid & 15;   // col group: cols tx*8..+7
    const int ty = tid >> 4;   // row group: rows ty*8..+7

    float acc[8][8];
#pragma unroll
    for (int i = 0; i < 8; i++)
#pragma unroll
        for (int j = 0; j < 8; j++) acc[i][j] = 0.0f;

#pragma unroll 8
    for (int k = 0; k < 128; k++) {
        float4 x0 = *(const float4*)(Xs + k * XSTR + ty * 8);
        float4 x1 = *(const float4*)(Xs + k * XSTR + ty * 8 + 4);
        float4 w0 = *(const float4*)(Ws + k * 128 + tx * 8);
        float4 w1 = *(const float4*)(Ws + k * 128 + tx * 8 + 4);
        float xv[8] = {x0.x, x0.y, x0.z, x0.w, x1.x, x1.y, x1.z, x1.w};
        float wv[8] = {w0.x, w0.y, w0.z, w0.w, w1.x, w1.y, w1.z, w1.w};
#pragma unroll
        for (int i = 0; i < 8; i++)
#pragma unroll
            for (int j = 0; j < 8; j++) acc[i][j] += xv[i] * wv[j];
    }

    // Epilogue (rows < NP always valid: out arrays are padded)
#pragma unroll
    for (int i = 0; i < 8; i++) {
        int r = row0 + ty * 8 + i;
        float* op = out + (size_t)r * 128 + tx * 8;
        if (EPI == 0) {
            const float* bp = bias_or_dis + tx * 8;
            float4 o0 = make_float4(acc[i][0] + bp[0], acc[i][1] + bp[1],
                                    acc[i][2] + bp[2], acc[i][3] + bp[3]);
            float4 o1 = make_float4(acc[i][4] + bp[4], acc[i][5] + bp[5],
                                    acc[i][6] + bp[6], acc[i][7] + bp[7]);
            *(float4*)op = o0;
            *(float4*)(op + 4) = o1;
        } else {
            float s = bias_or_dis[r];
            float4 o0 = make_float4(acc[i][0] * s, acc[i][1] * s,
                                    acc[i][2] * s, acc[i][3] * s);
            float4 o1 = make_float4(acc[i][4] * s, acc[i][5] * s,
                                    acc[i][6] * s, acc[i][7] * s);
            *(float4*)op = o0;
            *(float4*)(op + 4) = o1;
        }
    }
}

// ---------------------------------------------------------------------------
// CSR gather + fused finalize: one warp per node.
// h[n] = relu(dis[n] * (sum_{e in in(n)} g[col[e]] + g[n]) + b)
__global__ void gather_kernel(const float* __restrict__ b) {
    int w = (blockIdx.x * blockDim.x + threadIdx.x) >> 5;
    if (w >= NN) return;
    int lane = threadIdx.x & 31;
    int beg = g_rowptr[w];
    int end = g_rowptr[w + 1];

    const float4* G = (const float4*)g_g;
    float4 a0 = G[(size_t)w * 32 + lane];   // self term
    float4 a1 = make_float4(0.f, 0.f, 0.f, 0.f);

    int e = beg;
    while (e < end) {
        int cnt = min(end - e, 32);
        int c = (lane < cnt) ? g_col[e + lane] : 0;
        int i = 0;
        for (; i + 4 <= cnt; i += 4) {
            int s0 = __shfl_sync(0xffffffffu, c, i);
            int s1 = __shfl_sync(0xffffffffu, c, i + 1);
            int s2 = __shfl_sync(0xffffffffu, c, i + 2);
            int s3 = __shfl_sync(0xffffffffu, c, i + 3);
            float4 v0 = G[(size_t)s0 * 32 + lane];
            float4 v1 = G[(size_t)s1 * 32 + lane];
            float4 v2 = G[(size_t)s2 * 32 + lane];
            float4 v3 = G[(size_t)s3 * 32 + lane];
            a0.x += v0.x; a0.y += v0.y; a0.z += v0.z; a0.w += v0.w;
            a1.x += v1.x; a1.y += v1.y; a1.z += v1.z; a1.w += v1.w;
            a0.x += v2.x; a0.y += v2.y; a0.z += v2.z; a0.w += v2.w;
            a1.x += v3.x; a1.y += v3.y; a1.z += v3.z; a1.w += v3.w;
        }
        for (; i < cnt; i++) {
            int s0 = __shfl_sync(0xffffffffu, c, i);
            float4 v0 = G[(size_t)s0 * 32 + lane];
            a0.x += v0.x; a0.y += v0.y; a0.z += v0.z; a0.w += v0.w;
        }
        e += cnt;
    }
    a0.x += a1.x; a0.y += a1.y; a0.z += a1.z; a0.w += a1.w;

    float sc = g_dis[w];
    float4 bb = *(const float4*)(b + lane * 4);
    float4 o;
    o.x = fmaxf(fmaf(sc, a0.x, bb.x), 0.0f);
    o.y = fmaxf(fmaf(sc, a0.y, bb.y), 0.0f);
    o.z = fmaxf(fmaf(sc, a0.z, bb.z), 0.0f);
    o.w = fmaxf(fmaf(sc, a0.w, bb.w), 0.0f);
    *(float4*)(g_h + (size_t)w * 128 + lane * 4) = o;
}

// ---------------------------------------------------------------------------
// Pool: per-block smem accumulator [16][128] + counts, flushed with atomics
__global__ void pool_kernel(const int* __restrict__ batch) {
    __shared__ float s[GG * HH];
    __shared__ float c[GG];
    int tid = threadIdx.x;  // 128 threads
#pragma unroll
    for (int i = 0; i < GG; i++) s[i * HH + tid] = 0.0f;
    if (tid < GG) c[tid] = 0.0f;
    __syncthreads();

    for (int n = blockIdx.x; n < NN; n += gridDim.x) {
        int b = batch[n];
        s[b * HH + tid] += g_h[(size_t)n * HH + tid];
        if (tid == 0) c[b] += 1.0f;
    }
    __syncthreads();
#pragma unroll
    for (int i = 0; i < GG; i++) atomicAdd(&g_pool[i * HH + tid], s[i * HH + tid]);
    if (tid < GG) atomicAdd(&g_pool[GG * HH + tid], c[tid]);
}

// ---------------------------------------------------------------------------
// Head: pooled mean -> relu(@Wf1+bf1) -> @Wf2+bf2. Single block, 1024 threads.
__global__ void head_kernel(const float* __restrict__ Wf1,
                            const float* __restrict__ bf1,
                            const float* __restrict__ Wf2,
                            const float* __restrict__ bf2,
                            float* __restrict__ out) {
    __shared__ float P[GG * HH];
    __shared__ float Z[GG * 64];
    int tid = threadIdx.x;

    for (int i = tid; i < GG * HH; i += 1024) {
        float cnt = g_pool[GG * HH + i / HH];
        P[i] = g_pool[i] / fmaxf(cnt, 1.0f);
    }
    __syncthreads();

    {
        int g = tid >> 6;
        int j = tid & 63;
        float acc = bf1[j];
        const float* p = P + g * HH;
#pragma unroll 8
        for (int k = 0; k < HH; k++) acc += p[k] * Wf1[k * 64 + j];
        Z[g * 64 + j] = fmaxf(acc, 0.0f);
    }
    __syncthreads();

    if (tid < GG * CC) {
        int g = tid / CC;
        int c = tid % CC;
        float acc = bf2[c];
        const float* z = Z + g * 64;
#pragma unroll
        for (int j = 0; j < 64; j++) acc += z[j] * Wf2[j * CC + c];
        out[g * CC + c] = acc;
    }
}

// ---------------------------------------------------------------------------
extern "C" void kernel_launch(void* const* d_in, const int* in_sizes, int n_in,
                              void* d_out, int out_size) {
    const float* x = (const float*)d_in[0];
    const int* edge = (const int*)d_in[1];     // int32
    const int* batch = (const int*)d_in[2];    // int32
    const float* W_in = (const float*)d_in[3];
    const float* b_in = (const float*)d_in[4];
    const float* W1 = (const float*)d_in[5];
    const float* b1 = (const float*)d_in[6];
    const float* W2 = (const float*)d_in[7];
    const float* b2 = (const float*)d_in[8];
    const float* Wf1 = (const float*)d_in[9];
    const float* bf1 = (const float*)d_in[10];
    const float* Wf2 = (const float*)d_in[11];
    const float* bf2 = (const float*)d_in[12];
    float* out = (float*)d_out;

    const int* src = edge;
    const int* dst = edge + EE;

    void *p_deg, *p_pool, *p_h, *p_g, *p_dis;
    cudaGetSymbolAddress(&p_deg, g_deg);
    cudaGetSymbolAddress(&p_pool, g_pool);
    cudaGetSymbolAddress(&p_h, g_h);
    cudaGetSymbolAddress(&p_g, g_g);
    cudaGetSymbolAddress(&p_dis, g_dis);
    float* f_h = (float*)p_h;
    float* f_g = (float*)p_g;

    const int smemGemm = (128 * XSTR + 128 * 128) * sizeof(float);  // ~98KB
    cudaFuncSetAttribute(gemm128<0>, cudaFuncAttributeMaxDynamicSharedMemorySize, smemGemm);
    cudaFuncSetAttribute(gemm128<1>, cudaFuncAttributeMaxDynamicSharedMemorySize, smemGemm);

    // CSR build + dis
    cudaMemsetAsync(p_deg, 0, NN * sizeof(int));
    deg_kernel<<<(EE + 255) / 256, 256>>>(dst);
    dis_kernel<<<(NN + 255) / 256, 256>>>();
    scan_kernel<<<1, 1024>>>();
    fill_kernel<<<(EE + 255) / 256, 256>>>(src, dst);

    const int gemmGrid = NP / 64;  // 626

    // h0 = x @ W_in + b_in
    gemm128<0><<<gemmGrid, 128, smemGemm>>>(x, W_in, b_in, f_h, NN - 1);

    // Layer 1: g = (h @ W1) * dis;  h = relu(dis*(gather + self) + b1)
    gemm128<1><<<gemmGrid, 128, smemGemm>>>(f_h, W1, (const float*)p_dis, f_g, NP - 1);
    gather_kernel<<<(NN * 32 + 255) / 256, 256>>>(b1);

    // Layer 2
    gemm128<1><<<gemmGrid, 128, smemGemm>>>(f_h, W2, (const float*)p_dis, f_g, NP - 1);
    gather_kernel<<<(NN * 32 + 255) / 256, 256>>>(b2);

    // Pool + head
    cudaMemsetAsync(p_pool, 0, (GG * HH + GG) * sizeof(float));
    pool_kernel<<<256, 128>>>(batch);
    head_kernel<<<1, 1024>>>(Wf1, bf1, Wf2, bf2, out);
}